// round 3
// baseline (speedup 1.0000x reference)
#include <cuda_runtime.h>

#define N_NODES 50000
#define N_EDGES 800000
#define F_IN    500
#define H       96

// ---------------- device scratch (no allocations allowed) ----------------
__device__ float d_norm_out[N_NODES];
__device__ float d_norm_in[N_NODES];
__device__ int   d_deg_out[N_NODES];
__device__ int   d_deg_in[N_NODES];
__device__ int   d_row_ptr[N_NODES + 1];
__device__ int   d_cursor[N_NODES];
__device__ int   d_col[N_EDGES];          // src ids grouped by dst
__device__ float d_Y[N_NODES * H];        // x @ W1 (shared by both views)
__device__ float d_h[N_NODES * H];
__device__ float d_t[N_NODES * H];
__device__ float d_wvec[H];               // Wm @ ones
__device__ float d_bsum;                  // sum(bm)

// ---------------- degree / norm ----------------
__global__ void k_zero_deg() {
    int i = blockIdx.x * blockDim.x + threadIdx.x;
    if (i < N_NODES) { d_deg_out[i] = 0; d_deg_in[i] = 0; }
}

__global__ void k_count(const int* __restrict__ src, const int* __restrict__ dst) {
    int e = blockIdx.x * blockDim.x + threadIdx.x;
    if (e < N_EDGES) {
        atomicAdd(&d_deg_out[src[e]], 1);
        atomicAdd(&d_deg_in[dst[e]], 1);
    }
}

__global__ void k_norm() {
    int i = blockIdx.x * blockDim.x + threadIdx.x;
    if (i < N_NODES) {
        int dor = d_deg_out[i]; if (dor < 1) dor = 1;
        int din = d_deg_in[i];  if (din < 1) din = 1;
        d_norm_out[i] = rsqrtf((float)dor);
        d_norm_in[i]  = rsqrtf((float)din);
    }
}

// single-block exclusive scan of deg_in -> row_ptr (+ cursor copy)
__global__ void k_scan() {
    __shared__ int s[1024];
    __shared__ int carry;
    int tid = threadIdx.x;
    if (tid == 0) carry = 0;
    __syncthreads();
    int nch = (N_NODES + 1023) / 1024;
    for (int c = 0; c < nch; c++) {
        int i = c * 1024 + tid;
        int v = (i < N_NODES) ? d_deg_in[i] : 0;
        s[tid] = v;
        __syncthreads();
        #pragma unroll
        for (int off = 1; off < 1024; off <<= 1) {
            int t = (tid >= off) ? s[tid - off] : 0;
            __syncthreads();
            s[tid] += t;
            __syncthreads();
        }
        int base = carry;
        int excl = base + s[tid] - v;
        if (i < N_NODES) { d_row_ptr[i] = excl; d_cursor[i] = excl; }
        __syncthreads();
        if (tid == 0) carry = base + s[1023];
        __syncthreads();
    }
    if (tid == 0) d_row_ptr[N_NODES] = N_EDGES;
}

__global__ void k_build_csr(const int* __restrict__ src, const int* __restrict__ dst) {
    int e = blockIdx.x * blockDim.x + threadIdx.x;
    if (e < N_EDGES) {
        int d = dst[e];
        int pos = atomicAdd(&d_cursor[d], 1);
        d_col[pos] = src[e];
    }
}

// ---------------- fold Wm into a vector ----------------
__global__ void k_fold(const float* __restrict__ Wm, const float* __restrict__ bm) {
    int j = threadIdx.x;
    if (j < H) {
        float s = 0.f;
        #pragma unroll 4
        for (int k = 0; k < H; k++) s += Wm[j * H + k];
        d_wvec[j] = s;
    }
    if (j == H) {
        float s = 0.f;
        for (int k = 0; k < H; k++) s += bm[k];
        d_bsum = s;
    }
}

// ---------------- SGEMM: C[M,96] = (rowscale .* A[M,K]) @ B[K,96] ----------------
// BM=64, BN=96, BK=16, 256 threads, 4x6 micro-tile.
template <int BK>
__global__ void sgemm_n96(const float* __restrict__ A, int K,
                          const float* __restrict__ B,
                          const float* __restrict__ rowscale,
                          float* __restrict__ C, int M) {
    const int BM = 64, BN = 96;
    __shared__ float sA[BK][BM + 1];
    __shared__ float sB[BK][BN];

    int tid = threadIdx.x;
    int tx = tid % 16;          // 16 col groups (6 cols each)
    int ty = tid / 16;          // 16 row groups (4 rows each)
    int bm0 = blockIdx.x * BM;

    float acc[4][6];
    #pragma unroll
    for (int i = 0; i < 4; i++)
        #pragma unroll
        for (int j = 0; j < 6; j++) acc[i][j] = 0.f;

    for (int k0 = 0; k0 < K; k0 += BK) {
        // load A tile (transposed into smem), apply optional row scale
        #pragma unroll
        for (int i = 0; i < (BM * BK) / 256; i++) {
            int idx = tid + i * 256;
            int r = idx / BK, c = idx % BK;
            int gr = bm0 + r, gc = k0 + c;
            float v = 0.f;
            if (gr < M && gc < K) {
                v = A[gr * K + gc];
                if (rowscale) v *= rowscale[gr];
            }
            sA[c][r] = v;
        }
        // load B tile
        #pragma unroll
        for (int i = 0; i < (BK * BN) / 256; i++) {
            int idx = tid + i * 256;
            int r = idx / BN, c = idx % BN;
            int gk = k0 + r;
            sB[r][c] = (gk < K) ? B[gk * BN + c] : 0.f;
        }
        __syncthreads();

        #pragma unroll
        for (int kk = 0; kk < BK; kk++) {
            float a[4], b[6];
            #pragma unroll
            for (int i = 0; i < 4; i++) a[i] = sA[kk][ty * 4 + i];
            #pragma unroll
            for (int j = 0; j < 6; j++) b[j] = sB[kk][tx * 6 + j];
            #pragma unroll
            for (int i = 0; i < 4; i++)
                #pragma unroll
                for (int j = 0; j < 6; j++) acc[i][j] += a[i] * b[j];
        }
        __syncthreads();
    }

    #pragma unroll
    for (int i = 0; i < 4; i++) {
        int gr = bm0 + ty * 4 + i;
        if (gr < M) {
            #pragma unroll
            for (int j = 0; j < 6; j++)
                C[gr * 96 + tx * 6 + j] = acc[i][j];
        }
    }
}

// ---------------- view prep: h[i,:] = norm_out[i] * Y[g(i),:] ----------------
__global__ void k_scale_view(const int* __restrict__ perm, int view,
                             float* __restrict__ outp) {
    int idx = blockIdx.x * blockDim.x + threadIdx.x;
    if (idx >= N_NODES * H) return;
    int i = idx / H, j = idx % H;
    int g = view ? perm[i] : i;
    outp[idx] = d_norm_out[i] * d_Y[g * H + j];
}

// ---------------- fused CSR SpMM + norm_in + bias + PReLU ----------------
// one block (96 threads) per dst node; each thread owns one channel
__global__ void k_spmm(const float* __restrict__ in, float* __restrict__ out,
                       const float* __restrict__ b, const float* __restrict__ a) {
    int node = blockIdx.x;
    if (node >= N_NODES) return;
    int j = threadIdx.x;
    int s = d_row_ptr[node], e = d_row_ptr[node + 1];
    float acc = 0.f;
    int i = s;
    for (; i + 4 <= e; i += 4) {
        int c0 = d_col[i], c1 = d_col[i + 1], c2 = d_col[i + 2], c3 = d_col[i + 3];
        float v0 = in[c0 * H + j];
        float v1 = in[c1 * H + j];
        float v2 = in[c2 * H + j];
        float v3 = in[c3 * H + j];
        acc += (v0 + v1) + (v2 + v3);
    }
    for (; i < e; i++) acc += in[d_col[i] * H + j];
    float v = acc * d_norm_in[node] + b[j];
    out[node * H + j] = (v >= 0.f) ? v : a[j] * v;
}

// ---------------- output: out[i] = h2[i,:] . wvec + bsum ----------------
__global__ void k_out(const float* __restrict__ h2, float* __restrict__ out) {
    int gw = (blockIdx.x * blockDim.x + threadIdx.x) >> 5;
    int lane = threadIdx.x & 31;
    if (gw >= N_NODES) return;
    const float* row = h2 + gw * H;
    float s = row[lane] * d_wvec[lane]
            + row[lane + 32] * d_wvec[lane + 32]
            + row[lane + 64] * d_wvec[lane + 64];
    #pragma unroll
    for (int off = 16; off > 0; off >>= 1)
        s += __shfl_xor_sync(0xffffffffu, s, off);
    if (lane == 0) out[gw] = s + d_bsum;
}

// ---------------- launch ----------------
extern "C" void kernel_launch(void* const* d_in, const int* in_sizes, int n_in,
                              void* d_out, int out_size) {
    const float* x    = (const float*)d_in[0];
    const int*   src  = (const int*)d_in[1];
    const int*   dst  = (const int*)d_in[2];
    const int*   perm = (const int*)d_in[3];
    const float* W1   = (const float*)d_in[4];
    const float* b1   = (const float*)d_in[5];
    const float* a1   = (const float*)d_in[6];
    const float* W2   = (const float*)d_in[7];
    const float* b2   = (const float*)d_in[8];
    const float* a2   = (const float*)d_in[9];
    const float* Wm   = (const float*)d_in[10];
    const float* bm   = (const float*)d_in[11];
    float* out = (float*)d_out;

    float *hY, *hH, *hT, *hNormOut;
    cudaGetSymbolAddress((void**)&hY, d_Y);
    cudaGetSymbolAddress((void**)&hH, d_h);
    cudaGetSymbolAddress((void**)&hT, d_t);
    cudaGetSymbolAddress((void**)&hNormOut, d_norm_out);

    const int TB = 256;
    // graph structure
    k_zero_deg<<<(N_NODES + TB - 1) / TB, TB>>>();
    k_count<<<(N_EDGES + TB - 1) / TB, TB>>>(src, dst);
    k_norm<<<(N_NODES + TB - 1) / TB, TB>>>();
    k_scan<<<1, 1024>>>();
    k_build_csr<<<(N_EDGES + TB - 1) / TB, TB>>>(src, dst);
    k_fold<<<1, 128>>>(Wm, bm);

    // shared first-layer GEMM: Y = x @ W1
    int gm = (N_NODES + 63) / 64;
    sgemm_n96<16><<<gm, 256>>>(x, F_IN, W1, nullptr, hY, N_NODES);

    for (int v = 0; v < 2; v++) {
        // h = norm_out * Y[view rows]
        k_scale_view<<<(N_NODES * H + TB - 1) / TB, TB>>>(perm, v, hH);
        // layer 1 aggregate + bias + PReLU -> t
        k_spmm<<<N_NODES, H>>>(hH, hT, b1, a1);
        // layer 2 GEMM with fused norm_out row-scale: h = (t*norm_out) @ W2
        sgemm_n96<16><<<gm, 256>>>(hT, H, W2, hNormOut, hH, N_NODES);
        // layer 2 aggregate + bias + PReLU -> t
        k_spmm<<<N_NODES, H>>>(hH, hT, b2, a2);
        // projected row-sum
        k_out<<<(N_NODES * 32 + TB - 1) / TB, TB>>>(hT, out + v * N_NODES);
    }
}